// round 10
// baseline (speedup 1.0000x reference)
#include <cuda_runtime.h>
#include <cuda_fp16.h>
#include <cstdint>
#include <math.h>

#define BB   2
#define NN   2000
#define KK   32
#define HH   128
#define EPSC 1e-6f

// ---------------- device scratch (__device__ globals, no alloc) -------------
__device__ uint2 g_WQf[16 * 8 * 32];
__device__ uint2 g_W1f[16 * 8 * 32];
__device__ uint2 g_W2f[16 * 8 * 32];
// Fused value matrix Mfull[1024 x 128] fp16 fragments (Mfull = W_V(head) x W_O)
__device__ uint2 g_Mf[16 * 64 * 32];
__device__ __half g_Qh[4000 * 128];
__device__ __half g_Y [4000 * 1024];
__device__ float  g_dh[4000 * 128];

__device__ __forceinline__ unsigned int h2u(__half2 h) {
    return *(unsigned int*)&h;
}
__device__ __forceinline__ void cp_async16(void* dst_smem, const void* src) {
    unsigned int d = (unsigned int)__cvta_generic_to_shared(dst_smem);
    asm volatile("cp.async.cg.shared.global [%0], [%1], 16;" :: "r"(d), "l"(src));
}
__device__ __forceinline__ void cp_async_commit() {
    asm volatile("cp.async.commit_group;");
}
__device__ __forceinline__ void cp_async_wait0() {
    asm volatile("cp.async.wait_group 0;");
}

// ---------------- pack: weight fragments + Mfull ----------------------------
__global__ void pack_kernel(const float* __restrict__ WQ,
                            const float* __restrict__ WK1,
                            const float* __restrict__ WK2,
                            const float* __restrict__ WV,
                            const float* __restrict__ WO) {
    __shared__ float sWO[128 * 33];
    __shared__ float sWV[32 * 32];
    if (blockIdx.x < 16) {
        int t = blockIdx.x * 256 + threadIdx.x;   // 0..4095
        int lane = t & 31;
        int ks   = (t >> 5) & 7;
        int nt8  = t >> 8;
        int g    = lane >> 2;
        int tid4 = lane & 3;
        int n    = nt8 * 8 + g;
        int k0   = ks * 16 + tid4 * 2;
        uint2 uq, u1, u2;
        uq.x = h2u(__floats2half2_rn(WQ [n * 128 + k0],     WQ [n * 128 + k0 + 1]));
        uq.y = h2u(__floats2half2_rn(WQ [n * 128 + k0 + 8], WQ [n * 128 + k0 + 9]));
        u1.x = h2u(__floats2half2_rn(WK1[n * 128 + k0],     WK1[n * 128 + k0 + 1]));
        u1.y = h2u(__floats2half2_rn(WK1[n * 128 + k0 + 8], WK1[n * 128 + k0 + 9]));
        u2.x = h2u(__floats2half2_rn(WK2[n * 128 + k0],     WK2[n * 128 + k0 + 1]));
        u2.y = h2u(__floats2half2_rn(WK2[n * 128 + k0 + 8], WK2[n * 128 + k0 + 9]));
        g_WQf[t] = uq; g_W1f[t] = u1; g_W2f[t] = u2;
    } else {
        int bid = blockIdx.x - 16;        // 0..31
        int h   = bid >> 3;               // head
        int jc  = bid & 7;                // 32-wide j chunk within head
        int tid = threadIdx.x;
        for (int i = tid; i < 128 * 32; i += 256) {
            int o = i >> 5, ii = i & 31;
            sWO[o * 33 + ii] = WO[o * 128 + h * 32 + ii];
        }
        for (int i = tid; i < 32 * 32; i += 256) {
            int ii = i >> 5, jj = i & 31;
            sWV[ii * 32 + jj] = WV[(h * 32 + ii) * 256 + jc * 32 + jj];
        }
        __syncthreads();
        int o    = tid & 127;
        int jsel = tid >> 7;
        float wo[32];
#pragma unroll
        for (int ii = 0; ii < 32; ++ii) wo[ii] = sWO[o * 33 + ii];
        float m[16];
#pragma unroll
        for (int jj2 = 0; jj2 < 16; ++jj2) {
            int jj = jsel * 16 + jj2;
            float a = 0.f;
#pragma unroll
            for (int ii = 0; ii < 32; ++ii) a += sWV[ii * 32 + jj] * wo[ii];
            m[jj2] = a;
        }
        int ks = h * 16 + jc * 2 + jsel;
        int nt = o >> 3;
        int g  = o & 7;
#pragma unroll
        for (int tid4 = 0; tid4 < 4; ++tid4) {
            int k0l = tid4 * 2;
            uint2 u;
            u.x = h2u(__floats2half2_rn(m[k0l],     m[k0l + 1]));
            u.y = h2u(__floats2half2_rn(m[k0l + 8], m[k0l + 9]));
            g_Mf[(nt * 64 + ks) * 32 + (g << 2 | tid4)] = u;
        }
    }
}

// ---------------- PTX helpers ----------------
__device__ __forceinline__ void ldsm_x4(unsigned int* r, const void* p) {
    unsigned int a = (unsigned int)__cvta_generic_to_shared(p);
    asm volatile("ldmatrix.sync.aligned.m8n8.x4.shared.b16 {%0,%1,%2,%3}, [%4];"
                 : "=r"(r[0]), "=r"(r[1]), "=r"(r[2]), "=r"(r[3]) : "r"(a));
}
__device__ __forceinline__ void mma16816(float* d, const unsigned int* a,
                                         unsigned int b0, unsigned int b1) {
    asm volatile("mma.sync.aligned.m16n8k16.row.col.f32.f16.f16.f32 "
                 "{%0,%1,%2,%3}, {%4,%5,%6,%7}, {%8,%9}, {%0,%1,%2,%3};"
                 : "+f"(d[0]), "+f"(d[1]), "+f"(d[2]), "+f"(d[3])
                 : "r"(a[0]), "r"(a[1]), "r"(a[2]), "r"(a[3]), "r"(b0), "r"(b1));
}

// ---------------- qgemm: Q = h_V @ W_Q^T -> g_Qh (fp16 mma) -----------------
__global__ void __launch_bounds__(128)
qgemm_kernel(const float* __restrict__ h_V) {
    __shared__ __half sA[32 * 136];
    const int t    = threadIdx.x;
    const int w    = t >> 5;
    const int lane = t & 31;
    const int g    = lane >> 2;
    const int tid4 = lane & 3;
    const int node0 = blockIdx.x * 32;

    const float4* hv4 = (const float4*)h_V;
#pragma unroll
    for (int it = 0; it < 8; ++it) {
        int f4 = it * 128 + t;
        int r  = f4 >> 5, c4 = f4 & 31;
        float4 v = hv4[(size_t)(node0 + r) * 32 + c4];
        __half2* p = (__half2*)(sA + r * 136 + c4 * 4);
        p[0] = __floats2half2_rn(v.x, v.y);
        p[1] = __floats2half2_rn(v.z, v.w);
    }
    __syncthreads();

    float acc[2][4][4];
#pragma unroll
    for (int m = 0; m < 2; ++m)
#pragma unroll
        for (int n = 0; n < 4; ++n)
#pragma unroll
            for (int c = 0; c < 4; ++c) acc[m][n][c] = 0.f;

    const int arow = lane & 15, acol8 = (lane >> 4) * 8;
#pragma unroll
    for (int ks = 0; ks < 8; ++ks) {
        unsigned int a[2][4];
#pragma unroll
        for (int m = 0; m < 2; ++m)
            ldsm_x4(a[m], sA + (m * 16 + arow) * 136 + ks * 16 + acol8);
#pragma unroll
        for (int n = 0; n < 4; ++n) {
            uint2 b = g_WQf[(((w * 4 + n) * 8 + ks) * 32) + lane];
            mma16816(acc[0][n], a[0], b.x, b.y);
            mma16816(acc[1][n], a[1], b.x, b.y);
        }
    }
#pragma unroll
    for (int m = 0; m < 2; ++m)
#pragma unroll
        for (int n = 0; n < 4; ++n) {
            int col = w * 32 + n * 8 + tid4 * 2;
            int r0  = node0 + m * 16 + g;
            *(__half2*)&g_Qh[(size_t)r0 * 128 + col] =
                __floats2half2_rn(acc[m][n][0], acc[m][n][1]);
            *(__half2*)&g_Qh[(size_t)(r0 + 8) * 128 + col] =
                __floats2half2_rn(acc[m][n][2], acc[m][n][3]);
        }
}

// ---------------- attn: per node -> Y (R5 proven structure) -----------------
#define KROW 136
__global__ void __launch_bounds__(128, 4)
attn_kernel(const float* __restrict__ h_EV,
            const float* __restrict__ h_KV,
            const float* __restrict__ h_KE,
            const float* __restrict__ mask_attend) {
    extern __shared__ float smbuf[];
    float*  s_q      = smbuf;                    // 128
    float*  s_logits = s_q + 128;                // 128
    float*  s_ev     = s_logits + 128;           // 32*256 = 8192
    __half* s_keh    = (__half*)(s_ev + 8192);   // 32*KROW
    __half* s_kvh    = s_keh + 32 * KROW;        // 32*KROW

    const int bn   = blockIdx.x;
    const int t    = threadIdx.x;
    const int w    = t >> 5;
    const int lane = t & 31;
    const int g    = lane >> 2;
    const int tid4 = lane & 3;

    // prefetch EV (fp32) via cp.async — overlaps the whole mma phase
    {
        const float4* gev = (const float4*)(h_EV + (size_t)bn * KK * 256);
#pragma unroll
        for (int it = 0; it < 16; ++it) {
            int idx = it * 128 + t;              // 0..2047 float4s
            cp_async16(s_ev + idx * 4, gev + idx);
        }
        cp_async_commit();
    }

    // stage KE/KV as fp16
    {
        const float4* gke = (const float4*)(h_KE + (size_t)bn * KK * 128);
        const float4* gkv = (const float4*)(h_KV + (size_t)bn * KK * 128);
#pragma unroll
        for (int r = 0; r < 8; ++r) {
            int e4 = r * 128 + t;
            int k  = e4 >> 5;
            int j  = (e4 & 31) * 4;
            float4 a = gke[e4];
            float4 b = gkv[e4];
            uint2 ua, ub;
            ua.x = h2u(__floats2half2_rn(a.x, a.y));
            ua.y = h2u(__floats2half2_rn(a.z, a.w));
            ub.x = h2u(__floats2half2_rn(b.x, b.y));
            ub.y = h2u(__floats2half2_rn(b.z, b.w));
            *(uint2*)(s_keh + k * KROW + j) = ua;
            *(uint2*)(s_kvh + k * KROW + j) = ub;
        }
        s_q[t] = __half2float(g_Qh[(size_t)bn * 128 + t]);
    }
    __syncthreads();

    // K1/K2 mma (fp16 in, fp32 acc)
    float acc1[2][4][4], acc2[2][4][4];
#pragma unroll
    for (int m = 0; m < 2; ++m)
#pragma unroll
        for (int n = 0; n < 4; ++n)
#pragma unroll
            for (int c = 0; c < 4; ++c) { acc1[m][n][c] = 0.f; acc2[m][n][c] = 0.f; }

    const int arow = lane & 15, acol8 = (lane >> 4) * 8;
#pragma unroll
    for (int ks = 0; ks < 8; ++ks) {
        unsigned int a1[2][4], a2[2][4];
#pragma unroll
        for (int m = 0; m < 2; ++m) {
            ldsm_x4(a1[m], s_keh + (m * 16 + arow) * KROW + ks * 16 + acol8);
            ldsm_x4(a2[m], s_kvh + (m * 16 + arow) * KROW + ks * 16 + acol8);
        }
#pragma unroll
        for (int n = 0; n < 4; ++n) {
            int f = (((w * 4 + n) * 8 + ks) * 32) + lane;
            uint2 b1 = g_W1f[f];
            uint2 b2 = g_W2f[f];
            mma16816(acc1[0][n], a1[0], b1.x, b1.y);
            mma16816(acc1[1][n], a1[1], b1.x, b1.y);
            mma16816(acc2[0][n], a2[0], b2.x, b2.y);
            mma16816(acc2[1][n], a2[1], b2.x, b2.y);
        }
    }

    // logits[h=w][k] = (1/32) sum_i q*K1*K2
#pragma unroll
    for (int m = 0; m < 2; ++m) {
        float p0 = 0.f, p1 = 0.f;
#pragma unroll
        for (int n = 0; n < 4; ++n) {
            int j0 = w * 32 + n * 8 + tid4 * 2;
            float q0 = s_q[j0], q1 = s_q[j0 + 1];
            p0 += q0 * acc1[m][n][0] * acc2[m][n][0]
                + q1 * acc1[m][n][1] * acc2[m][n][1];
            p1 += q0 * acc1[m][n][2] * acc2[m][n][2]
                + q1 * acc1[m][n][3] * acc2[m][n][3];
        }
        p0 += __shfl_xor_sync(0xffffffffu, p0, 1);
        p0 += __shfl_xor_sync(0xffffffffu, p0, 2);
        p1 += __shfl_xor_sync(0xffffffffu, p1, 1);
        p1 += __shfl_xor_sync(0xffffffffu, p1, 2);
        if (tid4 == 0) {
            s_logits[w * 32 + m * 16 + g]     = p0 * (1.0f / 32.0f);
            s_logits[w * 32 + m * 16 + g + 8] = p1 * (1.0f / 32.0f);
        }
    }
    __syncwarp();

    // masked softmax: warp w = head, lane = neighbor k
    float attv;
    {
        float mk = mask_attend[(size_t)bn * KK + lane];
        float l  = s_logits[w * 32 + lane];
        l = (mk > 0.f) ? l : -3.402823466e38f;
        float mx = l;
#pragma unroll
        for (int off = 16; off > 0; off >>= 1)
            mx = fmaxf(mx, __shfl_xor_sync(0xffffffffu, mx, off));
        float e = expf(l - mx);
        float s = e;
#pragma unroll
        for (int off = 16; off > 0; off >>= 1)
            s += __shfl_xor_sync(0xffffffffu, s, off);
        attv = mk * e / s;
    }

    cp_async_wait0();
    __syncthreads();

    // y[w][j] = sum_k att_k * EV[k][j]
    {
        float4 y0 = make_float4(0.f, 0.f, 0.f, 0.f);
        float4 y1 = make_float4(0.f, 0.f, 0.f, 0.f);
#pragma unroll 4
        for (int k = 0; k < 32; ++k) {
            float a = __shfl_sync(0xffffffffu, attv, k);
            float4 e0 = *(const float4*)(s_ev + k * 256 + lane * 4);
            float4 e1 = *(const float4*)(s_ev + k * 256 + 128 + lane * 4);
            y0.x += a * e0.x; y0.y += a * e0.y; y0.z += a * e0.z; y0.w += a * e0.w;
            y1.x += a * e1.x; y1.y += a * e1.y; y1.z += a * e1.z; y1.w += a * e1.w;
        }
        uint2 u0, u1;
        u0.x = h2u(__floats2half2_rn(y0.x, y0.y));
        u0.y = h2u(__floats2half2_rn(y0.z, y0.w));
        u1.x = h2u(__floats2half2_rn(y1.x, y1.y));
        u1.y = h2u(__floats2half2_rn(y1.z, y1.w));
        ((uint2*)g_Y)[(size_t)bn * 256 + w * 64 + lane]      = u0;
        ((uint2*)g_Y)[(size_t)bn * 256 + w * 64 + 32 + lane] = u1;
    }
}

// ---------------- out GEMM: dh = Y @ Mfull (N-split across blocks) ----------
// grid 500 = 125 node-groups (32 nodes) x 4 col-groups (32 cols). 256 threads,
// 8 warps = 4 n-tiles (8 cols) x 2 K-halves (512). Writes dh fp32.
__global__ void __launch_bounds__(256)
outg_kernel() {
    extern __shared__ float smf[];
    float*  sRed = smf;                            // 2 * 32 * 36 floats
    __half* sY   = (__half*)(sRed + 2 * 32 * 36);  // 32 * 1032 halves

    const int t    = threadIdx.x;
    const int w    = t >> 5;
    const int lane = t & 31;
    const int g    = lane >> 2;
    const int tid4 = lane & 3;
    const int ng   = blockIdx.x >> 2;          // node group
    const int cg   = blockIdx.x & 3;           // 32-col group
    const int node0 = ng * 32;
    const int nt   = w & 3;                    // 8-col tile within group
    const int kh   = w >> 2;                   // K half

    // stage Y tile (64 KB) via cp.async
    {
#pragma unroll
        for (int it = 0; it < 16; ++it) {
            int f = it * 256 + t;              // 0..4095 (16B chunks)
            int r = f >> 7, c = f & 127;
            cp_async16(sY + r * 1032 + c * 8,
                       g_Y + (size_t)(node0 + r) * 1024 + c * 8);
        }
        cp_async_commit();
        cp_async_wait0();
    }
    __syncthreads();

    float acc[2][4];
#pragma unroll
    for (int m = 0; m < 2; ++m)
#pragma unroll
        for (int c = 0; c < 4; ++c) acc[m][c] = 0.f;

    const int arow = lane & 15, acol8 = (lane >> 4) * 8;
    const int gnt  = cg * 4 + nt;              // global 8-col tile (0..15)
    const int ks0  = kh * 32;
#pragma unroll 4
    for (int ksl = 0; ksl < 32; ++ksl) {
        int ks = ks0 + ksl;
        unsigned int a0[4], a1[4];
        ldsm_x4(a0, sY + arow * 1032 + ks * 16 + acol8);
        ldsm_x4(a1, sY + (16 + arow) * 1032 + ks * 16 + acol8);
        uint2 b = g_Mf[((gnt * 64 + ks) * 32) + lane];
        mma16816(acc[0], a0, b.x, b.y);
        mma16816(acc[1], a1, b.x, b.y);
    }

    // partial C -> smem: cols nt*8 + tid4*2 (+1), rows m*16 + g (+8)
    {
        float* base = sRed + kh * 32 * 36;
        int col = nt * 8 + tid4 * 2;
#pragma unroll
        for (int m = 0; m < 2; ++m) {
            int r0 = m * 16 + g;
            base[r0 * 36 + col]           = acc[m][0];
            base[r0 * 36 + col + 1]       = acc[m][1];
            base[(r0 + 8) * 36 + col]     = acc[m][2];
            base[(r0 + 8) * 36 + col + 1] = acc[m][3];
        }
    }
    __syncthreads();

    // reduce K-halves, write dh fp32: thread t -> row t>>3, float4 col t&7
    {
        int r  = t >> 3;
        int cq = t & 7;
        float4 a = *(float4*)&sRed[r * 36 + cq * 4];
        float4 b = *(float4*)&sRed[32 * 36 + r * 36 + cq * 4];
        float4 o;
        o.x = a.x + b.x; o.y = a.y + b.y; o.z = a.z + b.z; o.w = a.w + b.w;
        ((float4*)g_dh)[(size_t)(node0 + r) * 32 + cg * 8 + cq] = o;
    }
}

// ---------------- LN: out = LN(h_V + dh) ------------------------------------
// grid 500 x 256 threads, warp per node (8 nodes/block).
__global__ void __launch_bounds__(256)
ln_kernel(const float* __restrict__ h_V,
          const float* __restrict__ mask_V,
          const float* __restrict__ gain,
          const float* __restrict__ bias,
          float* __restrict__ out) {
    const int t    = threadIdx.x;
    const int w    = t >> 5;
    const int lane = t & 31;
    const int node = blockIdx.x * 8 + w;

    float4 dh = ((const float4*)g_dh)[(size_t)node * 32 + lane];
    float4 hv = ((const float4*)h_V)[(size_t)node * 32 + lane];
    float4 x;
    x.x = dh.x + hv.x; x.y = dh.y + hv.y; x.z = dh.z + hv.z; x.w = dh.w + hv.w;
    float sum = x.x + x.y + x.z + x.w;
    float sq  = x.x * x.x + x.y * x.y + x.z * x.z + x.w * x.w;
#pragma unroll
    for (int off = 16; off > 0; off >>= 1) {
        sum += __shfl_xor_sync(0xffffffffu, sum, off);
        sq  += __shfl_xor_sync(0xffffffffu, sq, off);
    }
    float mu  = sum * (1.f / 128.f);
    float var = (sq - sum * mu) * (1.f / 127.f);
    float sig = sqrtf(var + EPSC);
    float mk  = mask_V[node];
    float iv  = mk / (sig + EPSC);
    float4 gg = ((const float4*)gain)[lane];
    float4 bb = ((const float4*)bias)[lane];
    float4 o;
    o.x = (x.x - mu) * iv * gg.x + mk * bb.x;
    o.y = (x.y - mu) * iv * gg.y + mk * bb.y;
    o.z = (x.z - mu) * iv * gg.z + mk * bb.z;
    o.w = (x.w - mu) * iv * gg.w + mk * bb.w;
    ((float4*)out)[(size_t)node * 32 + lane] = o;
}

static const int ATTN_SMEM = (128 + 128 + 8192) * 4 + 2 * 32 * KROW * 2;
static const int OUTG_SMEM = (2 * 32 * 36) * 4 + 32 * 1032 * 2;

extern "C" void kernel_launch(void* const* d_in, const int* in_sizes, int n_in,
                              void* d_out, int out_size) {
    const float* h_V         = (const float*)d_in[0];
    const float* h_EV        = (const float*)d_in[1];
    const float* h_KV        = (const float*)d_in[2];
    const float* h_KE        = (const float*)d_in[3];
    const float* mask_V      = (const float*)d_in[4];
    const float* mask_attend = (const float*)d_in[5];
    const float* W_Q         = (const float*)d_in[6];
    const float* W_K1        = (const float*)d_in[7];
    const float* W_K2        = (const float*)d_in[8];
    const float* W_V         = (const float*)d_in[9];
    const float* W_O         = (const float*)d_in[10];
    const float* gain        = (const float*)d_in[11];
    const float* bias        = (const float*)d_in[12];
    float* out = (float*)d_out;

    pack_kernel<<<48, 256>>>(W_Q, W_K1, W_K2, W_V, W_O);
    qgemm_kernel<<<125, 128>>>(h_V);

    cudaFuncSetAttribute(attn_kernel,
                         cudaFuncAttributeMaxDynamicSharedMemorySize, ATTN_SMEM);
    attn_kernel<<<BB * NN, 128, ATTN_SMEM>>>(h_EV, h_KV, h_KE, mask_attend);

    cudaFuncSetAttribute(outg_kernel,
                         cudaFuncAttributeMaxDynamicSharedMemorySize, OUTG_SMEM);
    outg_kernel<<<500, 256, OUTG_SMEM>>>();

    ln_kernel<<<500, 256>>>(h_V, mask_V, gain, bias, out);
}

// round 11
// speedup vs baseline: 1.0264x; 1.0264x over previous
#include <cuda_runtime.h>
#include <cuda_fp16.h>
#include <cstdint>
#include <math.h>

#define BB   2
#define NN   2000
#define KK   32
#define HH   128
#define EPSC 1e-6f

// ---------------- device scratch (__device__ globals, no alloc) -------------
__device__ uint2 g_WQf[16 * 8 * 32];
__device__ uint2 g_W1f[16 * 8 * 32];
__device__ uint2 g_W2f[16 * 8 * 32];
// Fused value matrix Mfull[1024 x 128] fp16 fragments (Mfull = W_V(head) x W_O)
__device__ uint2 g_Mf[16 * 64 * 32];
__device__ __half g_Qh[4000 * 128];
__device__ __half g_Y [4000 * 1024];

__device__ __forceinline__ unsigned int h2u(__half2 h) {
    return *(unsigned int*)&h;
}
__device__ __forceinline__ void cp_async16(void* dst_smem, const void* src) {
    unsigned int d = (unsigned int)__cvta_generic_to_shared(dst_smem);
    asm volatile("cp.async.cg.shared.global [%0], [%1], 16;" :: "r"(d), "l"(src));
}
__device__ __forceinline__ void cp_async_commit() {
    asm volatile("cp.async.commit_group;");
}
__device__ __forceinline__ void cp_async_wait0() {
    asm volatile("cp.async.wait_group 0;");
}
// ---- TMA bulk 1D + mbarrier ----
__device__ __forceinline__ void mbar_init(void* mbar, unsigned int cnt) {
    unsigned int a = (unsigned int)__cvta_generic_to_shared(mbar);
    asm volatile("mbarrier.init.shared.b64 [%0], %1;" :: "r"(a), "r"(cnt) : "memory");
}
__device__ __forceinline__ void mbar_expect_tx(void* mbar, unsigned int bytes) {
    unsigned int a = (unsigned int)__cvta_generic_to_shared(mbar);
    asm volatile("mbarrier.arrive.expect_tx.shared.b64 _, [%0], %1;"
                 :: "r"(a), "r"(bytes) : "memory");
}
__device__ __forceinline__ void bulk_g2s(void* dst_smem, const void* src,
                                         unsigned int bytes, void* mbar) {
    unsigned int d = (unsigned int)__cvta_generic_to_shared(dst_smem);
    unsigned int m = (unsigned int)__cvta_generic_to_shared(mbar);
    asm volatile("cp.async.bulk.shared::cta.global.mbarrier::complete_tx::bytes "
                 "[%0], [%1], %2, [%3];"
                 :: "r"(d), "l"(src), "r"(bytes), "r"(m) : "memory");
}
__device__ __forceinline__ void mbar_wait(void* mbar, unsigned int parity) {
    unsigned int a = (unsigned int)__cvta_generic_to_shared(mbar);
    asm volatile(
        "{\n\t"
        ".reg .pred P1;\n\t"
        "WAIT_LOOP_%=:\n\t"
        "mbarrier.try_wait.parity.acquire.cta.shared::cta.b64 P1, [%0], %1, 0x989680;\n\t"
        "@P1 bra.uni WAIT_DONE_%=;\n\t"
        "bra.uni WAIT_LOOP_%=;\n\t"
        "WAIT_DONE_%=:\n\t"
        "}"
        :: "r"(a), "r"(parity) : "memory");
}

// ---------------- pack: weight fragments + Mfull ----------------------------
__global__ void pack_kernel(const float* __restrict__ WQ,
                            const float* __restrict__ WK1,
                            const float* __restrict__ WK2,
                            const float* __restrict__ WV,
                            const float* __restrict__ WO) {
    __shared__ float sWO[128 * 33];
    __shared__ float sWV[32 * 32];
    if (blockIdx.x < 16) {
        int t = blockIdx.x * 256 + threadIdx.x;   // 0..4095
        int lane = t & 31;
        int ks   = (t >> 5) & 7;
        int nt8  = t >> 8;
        int g    = lane >> 2;
        int tid4 = lane & 3;
        int n    = nt8 * 8 + g;
        int k0   = ks * 16 + tid4 * 2;
        uint2 uq, u1, u2;
        uq.x = h2u(__floats2half2_rn(WQ [n * 128 + k0],     WQ [n * 128 + k0 + 1]));
        uq.y = h2u(__floats2half2_rn(WQ [n * 128 + k0 + 8], WQ [n * 128 + k0 + 9]));
        u1.x = h2u(__floats2half2_rn(WK1[n * 128 + k0],     WK1[n * 128 + k0 + 1]));
        u1.y = h2u(__floats2half2_rn(WK1[n * 128 + k0 + 8], WK1[n * 128 + k0 + 9]));
        u2.x = h2u(__floats2half2_rn(WK2[n * 128 + k0],     WK2[n * 128 + k0 + 1]));
        u2.y = h2u(__floats2half2_rn(WK2[n * 128 + k0 + 8], WK2[n * 128 + k0 + 9]));
        g_WQf[t] = uq; g_W1f[t] = u1; g_W2f[t] = u2;
    } else {
        int bid = blockIdx.x - 16;        // 0..31
        int h   = bid >> 3;               // head
        int jc  = bid & 7;                // 32-wide j chunk within head
        int tid = threadIdx.x;
        for (int i = tid; i < 128 * 32; i += 256) {
            int o = i >> 5, ii = i & 31;
            sWO[o * 33 + ii] = WO[o * 128 + h * 32 + ii];
        }
        for (int i = tid; i < 32 * 32; i += 256) {
            int ii = i >> 5, jj = i & 31;
            sWV[ii * 32 + jj] = WV[(h * 32 + ii) * 256 + jc * 32 + jj];
        }
        __syncthreads();
        int o    = tid & 127;
        int jsel = tid >> 7;
        float wo[32];
#pragma unroll
        for (int ii = 0; ii < 32; ++ii) wo[ii] = sWO[o * 33 + ii];
        float m[16];
#pragma unroll
        for (int jj2 = 0; jj2 < 16; ++jj2) {
            int jj = jsel * 16 + jj2;
            float a = 0.f;
#pragma unroll
            for (int ii = 0; ii < 32; ++ii) a += sWV[ii * 32 + jj] * wo[ii];
            m[jj2] = a;
        }
        int ks = h * 16 + jc * 2 + jsel;
        int nt = o >> 3;
        int g  = o & 7;
#pragma unroll
        for (int tid4 = 0; tid4 < 4; ++tid4) {
            int k0l = tid4 * 2;
            uint2 u;
            u.x = h2u(__floats2half2_rn(m[k0l],     m[k0l + 1]));
            u.y = h2u(__floats2half2_rn(m[k0l + 8], m[k0l + 9]));
            g_Mf[(nt * 64 + ks) * 32 + (g << 2 | tid4)] = u;
        }
    }
}

// ---------------- PTX helpers ----------------
__device__ __forceinline__ void ldsm_x4(unsigned int* r, const void* p) {
    unsigned int a = (unsigned int)__cvta_generic_to_shared(p);
    asm volatile("ldmatrix.sync.aligned.m8n8.x4.shared.b16 {%0,%1,%2,%3}, [%4];"
                 : "=r"(r[0]), "=r"(r[1]), "=r"(r[2]), "=r"(r[3]) : "r"(a));
}
__device__ __forceinline__ void mma16816(float* d, const unsigned int* a,
                                         unsigned int b0, unsigned int b1) {
    asm volatile("mma.sync.aligned.m16n8k16.row.col.f32.f16.f16.f32 "
                 "{%0,%1,%2,%3}, {%4,%5,%6,%7}, {%8,%9}, {%0,%1,%2,%3};"
                 : "+f"(d[0]), "+f"(d[1]), "+f"(d[2]), "+f"(d[3])
                 : "r"(a[0]), "r"(a[1]), "r"(a[2]), "r"(a[3]), "r"(b0), "r"(b1));
}

// ---------------- qgemm: Q = h_V @ W_Q^T -> g_Qh (fp16 mma) -----------------
__global__ void __launch_bounds__(128)
qgemm_kernel(const float* __restrict__ h_V) {
    __shared__ __half sA[32 * 136];
    const int t    = threadIdx.x;
    const int w    = t >> 5;
    const int lane = t & 31;
    const int g    = lane >> 2;
    const int tid4 = lane & 3;
    const int node0 = blockIdx.x * 32;

    const float4* hv4 = (const float4*)h_V;
#pragma unroll
    for (int it = 0; it < 8; ++it) {
        int f4 = it * 128 + t;
        int r  = f4 >> 5, c4 = f4 & 31;
        float4 v = hv4[(size_t)(node0 + r) * 32 + c4];
        __half2* p = (__half2*)(sA + r * 136 + c4 * 4);
        p[0] = __floats2half2_rn(v.x, v.y);
        p[1] = __floats2half2_rn(v.z, v.w);
    }
    __syncthreads();

    float acc[2][4][4];
#pragma unroll
    for (int m = 0; m < 2; ++m)
#pragma unroll
        for (int n = 0; n < 4; ++n)
#pragma unroll
            for (int c = 0; c < 4; ++c) acc[m][n][c] = 0.f;

    const int arow = lane & 15, acol8 = (lane >> 4) * 8;
#pragma unroll
    for (int ks = 0; ks < 8; ++ks) {
        unsigned int a[2][4];
#pragma unroll
        for (int m = 0; m < 2; ++m)
            ldsm_x4(a[m], sA + (m * 16 + arow) * 136 + ks * 16 + acol8);
#pragma unroll
        for (int n = 0; n < 4; ++n) {
            uint2 b = g_WQf[(((w * 4 + n) * 8 + ks) * 32) + lane];
            mma16816(acc[0][n], a[0], b.x, b.y);
            mma16816(acc[1][n], a[1], b.x, b.y);
        }
    }
#pragma unroll
    for (int m = 0; m < 2; ++m)
#pragma unroll
        for (int n = 0; n < 4; ++n) {
            int col = w * 32 + n * 8 + tid4 * 2;
            int r0  = node0 + m * 16 + g;
            *(__half2*)&g_Qh[(size_t)r0 * 128 + col] =
                __floats2half2_rn(acc[m][n][0], acc[m][n][1]);
            *(__half2*)&g_Qh[(size_t)(r0 + 8) * 128 + col] =
                __floats2half2_rn(acc[m][n][2], acc[m][n][3]);
        }
}

// ---------------- attn: per node -> Y (EV via TMA bulk) ---------------------
#define KROW 136
__global__ void __launch_bounds__(128, 4)
attn_kernel(const float* __restrict__ h_EV,
            const float* __restrict__ h_KV,
            const float* __restrict__ h_KE,
            const float* __restrict__ mask_attend) {
    extern __shared__ float smbuf[];
    float*  s_mbar   = smbuf;                    // 32 floats (128B, mbar at [0])
    float*  s_q      = smbuf + 32;               // 128
    float*  s_logits = s_q + 128;                // 128
    float*  s_ev     = s_logits + 128;           // 32*256 = 8192 (16B aligned)
    __half* s_keh    = (__half*)(s_ev + 8192);   // 32*KROW
    __half* s_kvh    = s_keh + 32 * KROW;        // 32*KROW

    const int bn   = blockIdx.x;
    const int t    = threadIdx.x;
    const int w    = t >> 5;
    const int lane = t & 31;
    const int g    = lane >> 2;
    const int tid4 = lane & 3;

    // hoisted mask load (hides ~600cy before softmax)
    const float mk = mask_attend[(size_t)bn * KK + lane];

    // EV via single TMA bulk copy (32 KB) — no per-lane L1tex queue pressure
    if (t == 0) {
        mbar_init(s_mbar, 1);
        asm volatile("fence.proxy.async.shared::cta;" ::: "memory");
        mbar_expect_tx(s_mbar, KK * 256 * 4);
        bulk_g2s(s_ev, h_EV + (size_t)bn * KK * 256, KK * 256 * 4, s_mbar);
    }

    // stage KE/KV as fp16
    {
        const float4* gke = (const float4*)(h_KE + (size_t)bn * KK * 128);
        const float4* gkv = (const float4*)(h_KV + (size_t)bn * KK * 128);
#pragma unroll
        for (int r = 0; r < 8; ++r) {
            int e4 = r * 128 + t;
            int k  = e4 >> 5;
            int j  = (e4 & 31) * 4;
            float4 a = gke[e4];
            float4 b = gkv[e4];
            uint2 ua, ub;
            ua.x = h2u(__floats2half2_rn(a.x, a.y));
            ua.y = h2u(__floats2half2_rn(a.z, a.w));
            ub.x = h2u(__floats2half2_rn(b.x, b.y));
            ub.y = h2u(__floats2half2_rn(b.z, b.w));
            *(uint2*)(s_keh + k * KROW + j) = ua;
            *(uint2*)(s_kvh + k * KROW + j) = ub;
        }
        s_q[t] = __half2float(g_Qh[(size_t)bn * 128 + t]);
    }
    __syncthreads();

    // K1/K2 mma (fp16 in, fp32 acc)
    float acc1[2][4][4], acc2[2][4][4];
#pragma unroll
    for (int m = 0; m < 2; ++m)
#pragma unroll
        for (int n = 0; n < 4; ++n)
#pragma unroll
            for (int c = 0; c < 4; ++c) { acc1[m][n][c] = 0.f; acc2[m][n][c] = 0.f; }

    const int arow = lane & 15, acol8 = (lane >> 4) * 8;
#pragma unroll
    for (int ks = 0; ks < 8; ++ks) {
        unsigned int a1[2][4], a2[2][4];
#pragma unroll
        for (int m = 0; m < 2; ++m) {
            ldsm_x4(a1[m], s_keh + (m * 16 + arow) * KROW + ks * 16 + acol8);
            ldsm_x4(a2[m], s_kvh + (m * 16 + arow) * KROW + ks * 16 + acol8);
        }
#pragma unroll
        for (int n = 0; n < 4; ++n) {
            int f = (((w * 4 + n) * 8 + ks) * 32) + lane;
            uint2 b1 = g_W1f[f];
            uint2 b2 = g_W2f[f];
            mma16816(acc1[0][n], a1[0], b1.x, b1.y);
            mma16816(acc1[1][n], a1[1], b1.x, b1.y);
            mma16816(acc2[0][n], a2[0], b2.x, b2.y);
            mma16816(acc2[1][n], a2[1], b2.x, b2.y);
        }
    }

    // logits[h=w][k] = (1/32) sum_i q*K1*K2
#pragma unroll
    for (int m = 0; m < 2; ++m) {
        float p0 = 0.f, p1 = 0.f;
#pragma unroll
        for (int n = 0; n < 4; ++n) {
            int j0 = w * 32 + n * 8 + tid4 * 2;
            float q0 = s_q[j0], q1 = s_q[j0 + 1];
            p0 += q0 * acc1[m][n][0] * acc2[m][n][0]
                + q1 * acc1[m][n][1] * acc2[m][n][1];
            p1 += q0 * acc1[m][n][2] * acc2[m][n][2]
                + q1 * acc1[m][n][3] * acc2[m][n][3];
        }
        p0 += __shfl_xor_sync(0xffffffffu, p0, 1);
        p0 += __shfl_xor_sync(0xffffffffu, p0, 2);
        p1 += __shfl_xor_sync(0xffffffffu, p1, 1);
        p1 += __shfl_xor_sync(0xffffffffu, p1, 2);
        if (tid4 == 0) {
            s_logits[w * 32 + m * 16 + g]     = p0 * (1.0f / 32.0f);
            s_logits[w * 32 + m * 16 + g + 8] = p1 * (1.0f / 32.0f);
        }
    }
    __syncwarp();

    // masked softmax: warp w = head, lane = neighbor k (mk preloaded)
    float attv;
    {
        float l = s_logits[w * 32 + lane];
        l = (mk > 0.f) ? l : -3.402823466e38f;
        float mx = l;
#pragma unroll
        for (int off = 16; off > 0; off >>= 1)
            mx = fmaxf(mx, __shfl_xor_sync(0xffffffffu, mx, off));
        float e = expf(l - mx);
        float s = e;
#pragma unroll
        for (int off = 16; off > 0; off >>= 1)
            s += __shfl_xor_sync(0xffffffffu, s, off);
        attv = mk * e / s;
    }

    // wait for EV bulk copy
    mbar_wait(s_mbar, 0);
    __syncthreads();

    // y[w][j] = sum_k att_k * EV[k][j]
    {
        float4 y0 = make_float4(0.f, 0.f, 0.f, 0.f);
        float4 y1 = make_float4(0.f, 0.f, 0.f, 0.f);
#pragma unroll 4
        for (int k = 0; k < 32; ++k) {
            float a = __shfl_sync(0xffffffffu, attv, k);
            float4 e0 = *(const float4*)(s_ev + k * 256 + lane * 4);
            float4 e1 = *(const float4*)(s_ev + k * 256 + 128 + lane * 4);
            y0.x += a * e0.x; y0.y += a * e0.y; y0.z += a * e0.z; y0.w += a * e0.w;
            y1.x += a * e1.x; y1.y += a * e1.y; y1.z += a * e1.z; y1.w += a * e1.w;
        }
        uint2 u0, u1;
        u0.x = h2u(__floats2half2_rn(y0.x, y0.y));
        u0.y = h2u(__floats2half2_rn(y0.z, y0.w));
        u1.x = h2u(__floats2half2_rn(y1.x, y1.y));
        u1.y = h2u(__floats2half2_rn(y1.z, y1.w));
        ((uint2*)g_Y)[(size_t)bn * 256 + w * 64 + lane]      = u0;
        ((uint2*)g_Y)[(size_t)bn * 256 + w * 64 + 32 + lane] = u1;
    }
}

// ---------------- out: out = LN(h_V + Y @ Mfull) (R9 proven) ----------------
__global__ void __launch_bounds__(256)
out_kernel(const float* __restrict__ h_V,
           const float* __restrict__ mask_V,
           const float* __restrict__ gain,
           const float* __restrict__ bias,
           float* __restrict__ out) {
    extern __shared__ float smf[];
    float*  sRed = smf;                        // 2 * 32 * 132 floats
    __half* sY   = (__half*)(sRed + 2 * 32 * 132);  // 32 * 1032 halves

    const int t    = threadIdx.x;
    const int w    = t >> 5;
    const int lane = t & 31;
    const int g    = lane >> 2;
    const int tid4 = lane & 3;
    const int node0 = blockIdx.x * 32;
    const int nt4  = w & 3;                    // 32-col tile
    const int kh   = w >> 2;                   // K half

    {
#pragma unroll
        for (int it = 0; it < 16; ++it) {
            int f = it * 256 + t;              // 0..4095 (16B chunks)
            int r = f >> 7, c = f & 127;
            cp_async16(sY + r * 1032 + c * 8,
                       g_Y + (size_t)(node0 + r) * 1024 + c * 8);
        }
        cp_async_commit();
        cp_async_wait0();
    }
    __syncthreads();

    float acc[2][4][4];
#pragma unroll
    for (int m = 0; m < 2; ++m)
#pragma unroll
        for (int n = 0; n < 4; ++n)
#pragma unroll
            for (int c = 0; c < 4; ++c) acc[m][n][c] = 0.f;

    const int arow = lane & 15, acol8 = (lane >> 4) * 8;
    const int ks0  = kh * 32;

    unsigned int aA[2][4], aB[2][4];
    uint2 bA[4], bB[4];
#pragma unroll
    for (int m = 0; m < 2; ++m)
        ldsm_x4(aA[m], sY + (m * 16 + arow) * 1032 + ks0 * 16 + acol8);
#pragma unroll
    for (int n = 0; n < 4; ++n)
        bA[n] = g_Mf[(((nt4 * 4 + n) * 64 + ks0) * 32) + lane];

#pragma unroll
    for (int ksl = 0; ksl < 32; ++ksl) {
        unsigned int (*ac)[4] = (ksl & 1) ? aB : aA;
        unsigned int (*an)[4] = (ksl & 1) ? aA : aB;
        uint2* bc = (ksl & 1) ? bB : bA;
        uint2* bn = (ksl & 1) ? bA : bB;
        if (ksl < 31) {
            int ks = ks0 + ksl + 1;
#pragma unroll
            for (int m = 0; m < 2; ++m)
                ldsm_x4(an[m], sY + (m * 16 + arow) * 1032 + ks * 16 + acol8);
#pragma unroll
            for (int n = 0; n < 4; ++n)
                bn[n] = g_Mf[(((nt4 * 4 + n) * 64 + ks) * 32) + lane];
        }
#pragma unroll
        for (int n = 0; n < 4; ++n) {
            mma16816(acc[0][n], ac[0], bc[n].x, bc[n].y);
            mma16816(acc[1][n], ac[1], bc[n].x, bc[n].y);
        }
    }

#pragma unroll
    for (int m = 0; m < 2; ++m)
#pragma unroll
        for (int n = 0; n < 4; ++n) {
            int col = (nt4 * 4 + n) * 8 + tid4 * 2;
            int r0  = m * 16 + g;
            float* base = sRed + kh * 32 * 132;
            base[r0 * 132 + col]           = acc[m][n][0];
            base[r0 * 132 + col + 1]       = acc[m][n][1];
            base[(r0 + 8) * 132 + col]     = acc[m][n][2];
            base[(r0 + 8) * 132 + col + 1] = acc[m][n][3];
        }
    __syncthreads();

    {
        const float4* hv4 = (const float4*)h_V;
        const float4 gg = ((const float4*)gain)[lane];
        const float4 bb = ((const float4*)bias)[lane];
#pragma unroll
        for (int rr = 0; rr < 4; ++rr) {
            int r    = w * 4 + rr;
            int node = node0 + r;
            float4 c0 = *(float4*)&sRed[r * 132 + lane * 4];
            float4 c1 = *(float4*)&sRed[32 * 132 + r * 132 + lane * 4];
            float4 hv = hv4[(size_t)node * 32 + lane];
            float4 x;
            x.x = c0.x + c1.x + hv.x;
            x.y = c0.y + c1.y + hv.y;
            x.z = c0.z + c1.z + hv.z;
            x.w = c0.w + c1.w + hv.w;
            float sum = x.x + x.y + x.z + x.w;
            float sq  = x.x * x.x + x.y * x.y + x.z * x.z + x.w * x.w;
#pragma unroll
            for (int off = 16; off > 0; off >>= 1) {
                sum += __shfl_xor_sync(0xffffffffu, sum, off);
                sq  += __shfl_xor_sync(0xffffffffu, sq, off);
            }
            float mu  = sum * (1.f / 128.f);
            float var = (sq - sum * mu) * (1.f / 127.f);
            float sig = sqrtf(var + EPSC);
            float mk  = mask_V[node];
            float iv  = mk / (sig + EPSC);
            float4 o;
            o.x = (x.x - mu) * iv * gg.x + mk * bb.x;
            o.y = (x.y - mu) * iv * gg.y + mk * bb.y;
            o.z = (x.z - mu) * iv * gg.z + mk * bb.z;
            o.w = (x.w - mu) * iv * gg.w + mk * bb.w;
            ((float4*)out)[(size_t)node * 32 + lane] = o;
        }
    }
}

static const int ATTN_SMEM = (32 + 128 + 128 + 8192) * 4 + 2 * 32 * KROW * 2;
static const int OUT_SMEM  = (2 * 32 * 132) * 4 + 32 * 1032 * 2;

extern "C" void kernel_launch(void* const* d_in, const int* in_sizes, int n_in,
                              void* d_out, int out_size) {
    const float* h_V         = (const float*)d_in[0];
    const float* h_EV        = (const float*)d_in[1];
    const float* h_KV        = (const float*)d_in[2];
    const float* h_KE        = (const float*)d_in[3];
    const float* mask_V      = (const float*)d_in[4];
    const float* mask_attend = (const float*)d_in[5];
    const float* W_Q         = (const float*)d_in[6];
    const float* W_K1        = (const float*)d_in[7];
    const float* W_K2        = (const float*)d_in[8];
    const float* W_V         = (const float*)d_in[9];
    const float* W_O         = (const float*)d_in[10];
    const float* gain        = (const float*)d_in[11];
    const float* bias        = (const float*)d_in[12];
    float* out = (float*)d_out;

    pack_kernel<<<48, 256>>>(W_Q, W_K1, W_K2, W_V, W_O);
    qgemm_kernel<<<125, 128>>>(h_V);

    cudaFuncSetAttribute(attn_kernel,
                         cudaFuncAttributeMaxDynamicSharedMemorySize, ATTN_SMEM);
    attn_kernel<<<BB * NN, 128, ATTN_SMEM>>>(h_EV, h_KV, h_KE, mask_attend);

    cudaFuncSetAttribute(out_kernel,
                         cudaFuncAttributeMaxDynamicSharedMemorySize, OUT_SMEM);
    out_kernel<<<125, 256, OUT_SMEM>>>(h_V, mask_V, gain, bias, out);
}

// round 12
// speedup vs baseline: 1.0863x; 1.0583x over previous
#include <cuda_runtime.h>
#include <cuda_fp16.h>
#include <cstdint>
#include <math.h>

#define BB   2
#define NN   2000
#define KK   32
#define HH   128
#define EPSC 1e-6f

// ---------------- device scratch (__device__ globals, no alloc) -------------
__device__ uint2 g_WQf[16 * 8 * 32];
__device__ uint2 g_W1f[16 * 8 * 32];
__device__ uint2 g_W2f[16 * 8 * 32];
// Fused value matrix Mfull[1024 x 128] fp16 fragments (Mfull = W_V(head) x W_O)
__device__ uint2 g_Mf[16 * 64 * 32];
__device__ __half g_Qh[4000 * 128];
__device__ __half g_Y [4000 * 1024];

__device__ __forceinline__ unsigned int h2u(__half2 h) {
    return *(unsigned int*)&h;
}
__device__ __forceinline__ void cp_async16(void* dst_smem, const void* src) {
    unsigned int d = (unsigned int)__cvta_generic_to_shared(dst_smem);
    asm volatile("cp.async.cg.shared.global [%0], [%1], 16;" :: "r"(d), "l"(src));
}
__device__ __forceinline__ void cp_async_commit() {
    asm volatile("cp.async.commit_group;");
}
__device__ __forceinline__ void cp_async_wait0() {
    asm volatile("cp.async.wait_group 0;");
}

// ---------------- pack: weight fragments + Mfull ----------------------------
__global__ void pack_kernel(const float* __restrict__ WQ,
                            const float* __restrict__ WK1,
                            const float* __restrict__ WK2,
                            const float* __restrict__ WV,
                            const float* __restrict__ WO) {
    __shared__ float sWO[128 * 33];
    __shared__ float sWV[32 * 32];
    if (blockIdx.x < 16) {
        int t = blockIdx.x * 256 + threadIdx.x;   // 0..4095
        int lane = t & 31;
        int ks   = (t >> 5) & 7;
        int nt8  = t >> 8;
        int g    = lane >> 2;
        int tid4 = lane & 3;
        int n    = nt8 * 8 + g;
        int k0   = ks * 16 + tid4 * 2;
        uint2 uq, u1, u2;
        uq.x = h2u(__floats2half2_rn(WQ [n * 128 + k0],     WQ [n * 128 + k0 + 1]));
        uq.y = h2u(__floats2half2_rn(WQ [n * 128 + k0 + 8], WQ [n * 128 + k0 + 9]));
        u1.x = h2u(__floats2half2_rn(WK1[n * 128 + k0],     WK1[n * 128 + k0 + 1]));
        u1.y = h2u(__floats2half2_rn(WK1[n * 128 + k0 + 8], WK1[n * 128 + k0 + 9]));
        u2.x = h2u(__floats2half2_rn(WK2[n * 128 + k0],     WK2[n * 128 + k0 + 1]));
        u2.y = h2u(__floats2half2_rn(WK2[n * 128 + k0 + 8], WK2[n * 128 + k0 + 9]));
        g_WQf[t] = uq; g_W1f[t] = u1; g_W2f[t] = u2;
    } else {
        int bid = blockIdx.x - 16;        // 0..31
        int h   = bid >> 3;               // head
        int jc  = bid & 7;                // 32-wide j chunk within head
        int tid = threadIdx.x;
        for (int i = tid; i < 128 * 32; i += 256) {
            int o = i >> 5, ii = i & 31;
            sWO[o * 33 + ii] = WO[o * 128 + h * 32 + ii];
        }
        for (int i = tid; i < 32 * 32; i += 256) {
            int ii = i >> 5, jj = i & 31;
            sWV[ii * 32 + jj] = WV[(h * 32 + ii) * 256 + jc * 32 + jj];
        }
        __syncthreads();
        int o    = tid & 127;
        int jsel = tid >> 7;
        float wo[32];
#pragma unroll
        for (int ii = 0; ii < 32; ++ii) wo[ii] = sWO[o * 33 + ii];
        float m[16];
#pragma unroll
        for (int jj2 = 0; jj2 < 16; ++jj2) {
            int jj = jsel * 16 + jj2;
            float a = 0.f;
#pragma unroll
            for (int ii = 0; ii < 32; ++ii) a += sWV[ii * 32 + jj] * wo[ii];
            m[jj2] = a;
        }
        int ks = h * 16 + jc * 2 + jsel;
        int nt = o >> 3;
        int g  = o & 7;
#pragma unroll
        for (int tid4 = 0; tid4 < 4; ++tid4) {
            int k0l = tid4 * 2;
            uint2 u;
            u.x = h2u(__floats2half2_rn(m[k0l],     m[k0l + 1]));
            u.y = h2u(__floats2half2_rn(m[k0l + 8], m[k0l + 9]));
            g_Mf[(nt * 64 + ks) * 32 + (g << 2 | tid4)] = u;
        }
    }
}

// ---------------- PTX helpers ----------------
__device__ __forceinline__ void ldsm_x4(unsigned int* r, const void* p) {
    unsigned int a = (unsigned int)__cvta_generic_to_shared(p);
    asm volatile("ldmatrix.sync.aligned.m8n8.x4.shared.b16 {%0,%1,%2,%3}, [%4];"
                 : "=r"(r[0]), "=r"(r[1]), "=r"(r[2]), "=r"(r[3]) : "r"(a));
}
__device__ __forceinline__ void mma16816(float* d, const unsigned int* a,
                                         unsigned int b0, unsigned int b1) {
    asm volatile("mma.sync.aligned.m16n8k16.row.col.f32.f16.f16.f32 "
                 "{%0,%1,%2,%3}, {%4,%5,%6,%7}, {%8,%9}, {%0,%1,%2,%3};"
                 : "+f"(d[0]), "+f"(d[1]), "+f"(d[2]), "+f"(d[3])
                 : "r"(a[0]), "r"(a[1]), "r"(a[2]), "r"(a[3]), "r"(b0), "r"(b1));
}

// ---------------- qgemm: Q = h_V @ W_Q^T -> g_Qh (fp16 mma) -----------------
__global__ void __launch_bounds__(128)
qgemm_kernel(const float* __restrict__ h_V) {
    __shared__ __half sA[32 * 136];
    const int t    = threadIdx.x;
    const int w    = t >> 5;
    const int lane = t & 31;
    const int g    = lane >> 2;
    const int tid4 = lane & 3;
    const int node0 = blockIdx.x * 32;

    const float4* hv4 = (const float4*)h_V;
#pragma unroll
    for (int it = 0; it < 8; ++it) {
        int f4 = it * 128 + t;
        int r  = f4 >> 5, c4 = f4 & 31;
        float4 v = hv4[(size_t)(node0 + r) * 32 + c4];
        __half2* p = (__half2*)(sA + r * 136 + c4 * 4);
        p[0] = __floats2half2_rn(v.x, v.y);
        p[1] = __floats2half2_rn(v.z, v.w);
    }
    __syncthreads();

    float acc[2][4][4];
#pragma unroll
    for (int m = 0; m < 2; ++m)
#pragma unroll
        for (int n = 0; n < 4; ++n)
#pragma unroll
            for (int c = 0; c < 4; ++c) acc[m][n][c] = 0.f;

    const int arow = lane & 15, acol8 = (lane >> 4) * 8;
#pragma unroll
    for (int ks = 0; ks < 8; ++ks) {
        unsigned int a[2][4];
#pragma unroll
        for (int m = 0; m < 2; ++m)
            ldsm_x4(a[m], sA + (m * 16 + arow) * 136 + ks * 16 + acol8);
#pragma unroll
        for (int n = 0; n < 4; ++n) {
            uint2 b = g_WQf[(((w * 4 + n) * 8 + ks) * 32) + lane];
            mma16816(acc[0][n], a[0], b.x, b.y);
            mma16816(acc[1][n], a[1], b.x, b.y);
        }
    }
#pragma unroll
    for (int m = 0; m < 2; ++m)
#pragma unroll
        for (int n = 0; n < 4; ++n) {
            int col = w * 32 + n * 8 + tid4 * 2;
            int r0  = node0 + m * 16 + g;
            *(__half2*)&g_Qh[(size_t)r0 * 128 + col] =
                __floats2half2_rn(acc[m][n][0], acc[m][n][1]);
            *(__half2*)&g_Qh[(size_t)(r0 + 8) * 128 + col] =
                __floats2half2_rn(acc[m][n][2], acc[m][n][3]);
        }
}

// ---------------- attn: per node -> Y ----------------------------------------
#define KROW 136
__global__ void __launch_bounds__(128, 4)
attn_kernel(const float* __restrict__ h_EV,
            const float* __restrict__ h_KV,
            const float* __restrict__ h_KE,
            const float* __restrict__ mask_attend) {
    extern __shared__ float smbuf[];
    float*  s_q      = smbuf;                    // 128
    float*  s_logits = s_q + 128;                // 128
    float*  s_att    = s_logits + 128;           // 128
    float*  s_ev     = s_att + 128;              // 32*256 = 8192
    __half* s_keh    = (__half*)(s_ev + 8192);   // 32*KROW
    __half* s_kvh    = s_keh + 32 * KROW;        // 32*KROW

    const int bn   = blockIdx.x;
    const int t    = threadIdx.x;
    const int w    = t >> 5;
    const int lane = t & 31;
    const int g    = lane >> 2;
    const int tid4 = lane & 3;

    // hoisted mask load (hides the gmem latency before softmax)
    const float mk = mask_attend[(size_t)bn * KK + lane];

    // prefetch EV (fp32) via cp.async — overlaps the whole mma phase
    {
        const float4* gev = (const float4*)(h_EV + (size_t)bn * KK * 256);
#pragma unroll
        for (int it = 0; it < 16; ++it) {
            int idx = it * 128 + t;              // 0..2047 float4s
            cp_async16(s_ev + idx * 4, gev + idx);
        }
        cp_async_commit();
    }

    // stage KE/KV as fp16
    {
        const float4* gke = (const float4*)(h_KE + (size_t)bn * KK * 128);
        const float4* gkv = (const float4*)(h_KV + (size_t)bn * KK * 128);
#pragma unroll
        for (int r = 0; r < 8; ++r) {
            int e4 = r * 128 + t;
            int k  = e4 >> 5;
            int j  = (e4 & 31) * 4;
            float4 a = gke[e4];
            float4 b = gkv[e4];
            uint2 ua, ub;
            ua.x = h2u(__floats2half2_rn(a.x, a.y));
            ua.y = h2u(__floats2half2_rn(a.z, a.w));
            ub.x = h2u(__floats2half2_rn(b.x, b.y));
            ub.y = h2u(__floats2half2_rn(b.z, b.w));
            *(uint2*)(s_keh + k * KROW + j) = ua;
            *(uint2*)(s_kvh + k * KROW + j) = ub;
        }
        s_q[t] = __half2float(g_Qh[(size_t)bn * 128 + t]);
    }
    __syncthreads();

    // K1/K2 mma (fp16 in, fp32 acc)
    float acc1[2][4][4], acc2[2][4][4];
#pragma unroll
    for (int m = 0; m < 2; ++m)
#pragma unroll
        for (int n = 0; n < 4; ++n)
#pragma unroll
            for (int c = 0; c < 4; ++c) { acc1[m][n][c] = 0.f; acc2[m][n][c] = 0.f; }

    const int arow = lane & 15, acol8 = (lane >> 4) * 8;
#pragma unroll
    for (int ks = 0; ks < 8; ++ks) {
        unsigned int a1[2][4], a2[2][4];
#pragma unroll
        for (int m = 0; m < 2; ++m) {
            ldsm_x4(a1[m], s_keh + (m * 16 + arow) * KROW + ks * 16 + acol8);
            ldsm_x4(a2[m], s_kvh + (m * 16 + arow) * KROW + ks * 16 + acol8);
        }
#pragma unroll
        for (int n = 0; n < 4; ++n) {
            int f = (((w * 4 + n) * 8 + ks) * 32) + lane;
            uint2 b1 = g_W1f[f];
            uint2 b2 = g_W2f[f];
            mma16816(acc1[0][n], a1[0], b1.x, b1.y);
            mma16816(acc1[1][n], a1[1], b1.x, b1.y);
            mma16816(acc2[0][n], a2[0], b2.x, b2.y);
            mma16816(acc2[1][n], a2[1], b2.x, b2.y);
        }
    }

    // logits[h=w][k] = (1/32) sum_i q*K1*K2
#pragma unroll
    for (int m = 0; m < 2; ++m) {
        float p0 = 0.f, p1 = 0.f;
#pragma unroll
        for (int n = 0; n < 4; ++n) {
            int j0 = w * 32 + n * 8 + tid4 * 2;
            float q0 = s_q[j0], q1 = s_q[j0 + 1];
            p0 += q0 * acc1[m][n][0] * acc2[m][n][0]
                + q1 * acc1[m][n][1] * acc2[m][n][1];
            p1 += q0 * acc1[m][n][2] * acc2[m][n][2]
                + q1 * acc1[m][n][3] * acc2[m][n][3];
        }
        p0 += __shfl_xor_sync(0xffffffffu, p0, 1);
        p0 += __shfl_xor_sync(0xffffffffu, p0, 2);
        p1 += __shfl_xor_sync(0xffffffffu, p1, 1);
        p1 += __shfl_xor_sync(0xffffffffu, p1, 2);
        if (tid4 == 0) {
            s_logits[w * 32 + m * 16 + g]     = p0 * (1.0f / 32.0f);
            s_logits[w * 32 + m * 16 + g + 8] = p1 * (1.0f / 32.0f);
        }
    }
    __syncwarp();

    // masked softmax: warp w = head, lane = neighbor k -> s_att
    {
        float l = s_logits[w * 32 + lane];
        l = (mk > 0.f) ? l : -3.402823466e38f;
        float mx = l;
#pragma unroll
        for (int off = 16; off > 0; off >>= 1)
            mx = fmaxf(mx, __shfl_xor_sync(0xffffffffu, mx, off));
        float e = expf(l - mx);
        float s = e;
#pragma unroll
        for (int off = 16; off > 0; off >>= 1)
            s += __shfl_xor_sync(0xffffffffu, s, off);
        s_att[w * 32 + lane] = mk * e / s;
    }

    cp_async_wait0();
    __syncthreads();

    // y[h][c] = sum_k att[h][k] * EV[k][c] for ALL 4 heads; thread t owns
    // cols [2t, 2t+2) -> each EV smem element read exactly ONCE per block
    // (4x less LDS traffic than warp-per-head).
    {
        float2 a0 = make_float2(0.f, 0.f), a1 = make_float2(0.f, 0.f);
        float2 a2 = make_float2(0.f, 0.f), a3 = make_float2(0.f, 0.f);
#pragma unroll 8
        for (int k = 0; k < 32; ++k) {
            float2 e  = *(const float2*)(s_ev + k * 256 + t * 2);
            float w0 = s_att[k];
            float w1 = s_att[32 + k];
            float w2 = s_att[64 + k];
            float w3 = s_att[96 + k];
            a0.x += w0 * e.x; a0.y += w0 * e.y;
            a1.x += w1 * e.x; a1.y += w1 * e.y;
            a2.x += w2 * e.x; a2.y += w2 * e.y;
            a3.x += w3 * e.x; a3.y += w3 * e.y;
        }
        __half* gy = g_Y + (size_t)bn * 1024 + t * 2;
        *(__half2*)(gy)       = __floats2half2_rn(a0.x, a0.y);
        *(__half2*)(gy + 256) = __floats2half2_rn(a1.x, a1.y);
        *(__half2*)(gy + 512) = __floats2half2_rn(a2.x, a2.y);
        *(__half2*)(gy + 768) = __floats2half2_rn(a3.x, a3.y);
    }
}

// ---------------- out: out = LN(h_V + Y @ Mfull) (R9 proven) ----------------
__global__ void __launch_bounds__(256)
out_kernel(const float* __restrict__ h_V,
           const float* __restrict__ mask_V,
           const float* __restrict__ gain,
           const float* __restrict__ bias,
           float* __restrict__ out) {
    extern __shared__ float smf[];
    float*  sRed = smf;                        // 2 * 32 * 132 floats
    __half* sY   = (__half*)(sRed + 2 * 32 * 132);  // 32 * 1032 halves

    const int t    = threadIdx.x;
    const int w    = t >> 5;
    const int lane = t & 31;
    const int g    = lane >> 2;
    const int tid4 = lane & 3;
    const int node0 = blockIdx.x * 32;
    const int nt4  = w & 3;                    // 32-col tile
    const int kh   = w >> 2;                   // K half

    {
#pragma unroll
        for (int it = 0; it < 16; ++it) {
            int f = it * 256 + t;              // 0..4095 (16B chunks)
            int r = f >> 7, c = f & 127;
            cp_async16(sY + r * 1032 + c * 8,
                       g_Y + (size_t)(node0 + r) * 1024 + c * 8);
        }
        cp_async_commit();
        cp_async_wait0();
    }
    __syncthreads();

    float acc[2][4][4];
#pragma unroll
    for (int m = 0; m < 2; ++m)
#pragma unroll
        for (int n = 0; n < 4; ++n)
#pragma unroll
            for (int c = 0; c < 4; ++c) acc[m][n][c] = 0.f;

    const int arow = lane & 15, acol8 = (lane >> 4) * 8;
    const int ks0  = kh * 32;

    unsigned int aA[2][4], aB[2][4];
    uint2 bA[4], bB[4];
#pragma unroll
    for (int m = 0; m < 2; ++m)
        ldsm_x4(aA[m], sY + (m * 16 + arow) * 1032 + ks0 * 16 + acol8);
#pragma unroll
    for (int n = 0; n < 4; ++n)
        bA[n] = g_Mf[(((nt4 * 4 + n) * 64 + ks0) * 32) + lane];

#pragma unroll
    for (int ksl = 0; ksl < 32; ++ksl) {
        unsigned int (*ac)[4] = (ksl & 1) ? aB : aA;
        unsigned int (*an)[4] = (ksl & 1) ? aA : aB;
        uint2* bc = (ksl & 1) ? bB : bA;
        uint2* bn = (ksl & 1) ? bA : bB;
        if (ksl < 31) {
            int ks = ks0 + ksl + 1;
#pragma unroll
            for (int m = 0; m < 2; ++m)
                ldsm_x4(an[m], sY + (m * 16 + arow) * 1032 + ks * 16 + acol8);
#pragma unroll
            for (int n = 0; n < 4; ++n)
                bn[n] = g_Mf[(((nt4 * 4 + n) * 64 + ks) * 32) + lane];
        }
#pragma unroll
        for (int n = 0; n < 4; ++n) {
            mma16816(acc[0][n], ac[0], bc[n].x, bc[n].y);
            mma16816(acc[1][n], ac[1], bc[n].x, bc[n].y);
        }
    }

#pragma unroll
    for (int m = 0; m < 2; ++m)
#pragma unroll
        for (int n = 0; n < 4; ++n) {
            int col = (nt4 * 4 + n) * 8 + tid4 * 2;
            int r0  = m * 16 + g;
            float* base = sRed + kh * 32 * 132;
            base[r0 * 132 + col]           = acc[m][n][0];
            base[r0 * 132 + col + 1]       = acc[m][n][1];
            base[(r0 + 8) * 132 + col]     = acc[m][n][2];
            base[(r0 + 8) * 132 + col + 1] = acc[m][n][3];
        }
    __syncthreads();

    {
        const float4* hv4 = (const float4*)h_V;
        const float4 gg = ((const float4*)gain)[lane];
        const float4 bb = ((const float4*)bias)[lane];
#pragma unroll
        for (int rr = 0; rr < 4; ++rr) {
            int r    = w * 4 + rr;
            int node = node0 + r;
            float4 c0 = *(float4*)&sRed[r * 132 + lane * 4];
            float4 c1 = *(float4*)&sRed[32 * 132 + r * 132 + lane * 4];
            float4 hv = hv4[(size_t)node * 32 + lane];
            float4 x;
            x.x = c0.x + c1.x + hv.x;
            x.y = c0.y + c1.y + hv.y;
            x.z = c0.z + c1.z + hv.z;
            x.w = c0.w + c1.w + hv.w;
            float sum = x.x + x.y + x.z + x.w;
            float sq  = x.x * x.x + x.y * x.y + x.z * x.z + x.w * x.w;
#pragma unroll
            for (int off = 16; off > 0; off >>= 1) {
                sum += __shfl_xor_sync(0xffffffffu, sum, off);
                sq  += __shfl_xor_sync(0xffffffffu, sq, off);
            }
            float mu  = sum * (1.f / 128.f);
            float var = (sq - sum * mu) * (1.f / 127.f);
            float sig = sqrtf(var + EPSC);
            float mk  = mask_V[node];
            float iv  = mk / (sig + EPSC);
            float4 o;
            o.x = (x.x - mu) * iv * gg.x + mk * bb.x;
            o.y = (x.y - mu) * iv * gg.y + mk * bb.y;
            o.z = (x.z - mu) * iv * gg.z + mk * bb.z;
            o.w = (x.w - mu) * iv * gg.w + mk * bb.w;
            ((float4*)out)[(size_t)node * 32 + lane] = o;
        }
    }
}

static const int ATTN_SMEM = (128 + 128 + 128 + 8192) * 4 + 2 * 32 * KROW * 2;
static const int OUT_SMEM  = (2 * 32 * 132) * 4 + 32 * 1032 * 2;

extern "C" void kernel_launch(void* const* d_in, const int* in_sizes, int n_in,
                              void* d_out, int out_size) {
    const float* h_V         = (const float*)d_in[0];
    const float* h_EV        = (const float*)d_in[1];
    const float* h_KV        = (const float*)d_in[2];
    const float* h_KE        = (const float*)d_in[3];
    const float* mask_V      = (const float*)d_in[4];
    const float* mask_attend = (const float*)d_in[5];
    const float* W_Q         = (const float*)d_in[6];
    const float* W_K1        = (const float*)d_in[7];
    const float* W_K2        = (const float*)d_in[8];
    const float* W_V         = (const float*)d_in[9];
    const float* W_O         = (const float*)d_in[10];
    const float* gain        = (const float*)d_in[11];
    const float* bias        = (const float*)d_in[12];
    float* out = (float*)d_out;

    pack_kernel<<<48, 256>>>(W_Q, W_K1, W_K2, W_V, W_O);
    qgemm_kernel<<<125, 128>>>(h_V);

    cudaFuncSetAttribute(attn_kernel,
                         cudaFuncAttributeMaxDynamicSharedMemorySize, ATTN_SMEM);
    attn_kernel<<<BB * NN, 128, ATTN_SMEM>>>(h_EV, h_KV, h_KE, mask_attend);

    cudaFuncSetAttribute(out_kernel,
                         cudaFuncAttributeMaxDynamicSharedMemorySize, OUT_SMEM);
    out_kernel<<<125, 256, OUT_SMEM>>>(h_V, mask_V, gain, bias, out);
}